// round 16
// baseline (speedup 1.0000x reference)
#include <cuda_runtime.h>
#include <cuda_fp16.h>
#include <cstdint>
#include <math.h>

#define N_TOK 4096
#define D_DIM 512
#define ND (N_TOK * D_DIM)
#define NN ((size_t)N_TOK * N_TOK)
#define WSZ (D_DIM * D_DIM)

// ---------------- scratch (device globals; no cudaMalloc allowed) ----------
static __device__ float g_X1[2][ND];
static __device__ float g_X2[2][ND];
static __device__ float g_rsum[2][N_TOK];

static __device__ __align__(16) __half g_Lh[ND], g_Rh[ND];
static __device__ __align__(16) __half g_Qh[2][ND], g_Kh[2][ND];
static __device__ __align__(16) __half g_Vth[2][ND];
static __device__ __align__(16) __half g_Sh[2][NN];
static __device__ __align__(16) __half g_X2h[2][ND];
static __device__ __align__(16) __half g_Hh[2][ND];
static __device__ __align__(16) __half g_Wth[10][WSZ];

// ---------------- helpers ---------------------------------------------------
__device__ __forceinline__ uint32_t smem_u32(const void* p) {
    uint32_t a;
    asm("{ .reg .u64 t; cvta.to.shared.u64 t, %1; cvt.u32.u64 %0, t; }" : "=r"(a) : "l"(p));
    return a;
}
__device__ __forceinline__ void cpasync16(uint32_t s, const void* g) {
    asm volatile("cp.async.cg.shared.global [%0], [%1], 16;" :: "r"(s), "l"(g) : "memory");
}
__device__ __forceinline__ void cp_commit() {
    asm volatile("cp.async.commit_group;" ::: "memory");
}
template<int N>
__device__ __forceinline__ void cp_wait() {
    asm volatile("cp.async.wait_group %0;" :: "n"(N) : "memory");
}
__device__ __forceinline__ void ldmx4(uint32_t* r, uint32_t a) {
    asm volatile("ldmatrix.sync.aligned.m8n8.x4.shared.b16 {%0,%1,%2,%3}, [%4];"
                 : "=r"(r[0]), "=r"(r[1]), "=r"(r[2]), "=r"(r[3]) : "r"(a));
}
__device__ __forceinline__ void mma16816(float* c, const uint32_t* a, const uint32_t* b) {
    asm volatile(
        "mma.sync.aligned.m16n8k16.row.col.f32.f16.f16.f32 "
        "{%0,%1,%2,%3},{%4,%5,%6,%7},{%8,%9},{%0,%1,%2,%3};"
        : "+f"(c[0]), "+f"(c[1]), "+f"(c[2]), "+f"(c[3])
        : "r"(a[0]), "r"(a[1]), "r"(a[2]), "r"(a[3]), "r"(b[0]), "r"(b[1]));
}

// ---------------- elementwise fp32 -> fp16 convert (batched) ---------------
struct CvArgs { const float* in[2]; __half* o[2]; };

__global__ __launch_bounds__(256) void cvt_kernel(CvArgs a, int n4)
{
    const float* __restrict__ in = a.in[blockIdx.y];
    __half* __restrict__ o = a.o[blockIdx.y];
    int i = blockIdx.x * 256 + threadIdx.x;
    if (i >= n4) return;
    float4 v = ((const float4*)in)[i];
    ((__half2*)o)[2 * i]     = __floats2half2_rn(v.x, v.y);
    ((__half2*)o)[2 * i + 1] = __floats2half2_rn(v.z, v.w);
}

// ---------------- batched transpose + convert (weights only) ---------------
struct TcArgs { const float* in[10]; __half* oh[10]; };

__global__ void tconv_kernel(TcArgs a, int rows, int cols)
{
    const float* __restrict__ in = a.in[blockIdx.z];
    __half* __restrict__ oh = a.oh[blockIdx.z];
    __shared__ float t[32][33];
    const int bx = blockIdx.x << 5, by = blockIdx.y << 5;
    const int tx = threadIdx.x, ty = threadIdx.y;  // 32 x 8
#pragma unroll
    for (int j = 0; j < 32; j += 8)
        t[ty + j][tx] = in[(size_t)(by + ty + j) * cols + bx + tx];
    __syncthreads();
#pragma unroll
    for (int j = 0; j < 32; j += 8) {
        float v = t[tx][ty + j];
        oh[(size_t)(bx + ty + j) * rows + by + tx] = __float2half_rn(v);
    }
}

// ---------------- HMMA fp16 GEMM (batched via grid.z) ----------------------
// C[M,N] = A[M,K] @ B[N,K]^T, fp16 operands, fp32 accum.
// CTA 128x128, BK=64, 8 warps (2x4), warp 64x32, 3-stage cp.async, 2 CTAs/SM.
// swap=1: blockIdx.x indexes M-tiles, blockIdx.y indexes N-tiles.
enum { EPI_NONE = 0, EPI_GAUSS = 1, EPI_BIAS = 2, EPI_RELU = 3, EPI_RESID = 4, EPI_NORM = 5 };

struct GArg {
    const __half *Ah, *Bh;
    float* C;              // fp32 out (or rowsum accumulator for score epis)
    __half* Oh;            // fp16 out
    const float* bias;     // bias matrix / bias vec / rowsum (EPI_NORM)
    const float* resid;
    float scale;
    int epi;
    int swap;
};
struct GArgs { GArg a[4]; };

__device__ __forceinline__ void emit2(const GArg& g, int row, int col, float x, float y, int Ncols)
{
    if (g.epi == EPI_RELU) {
        float2 b = *(const float2*)(g.bias + col);
        x = fmaxf(x + b.x, 0.f);
        y = fmaxf(y + b.y, 0.f);
    } else if (g.epi == EPI_RESID) {
        float2 b = *(const float2*)(g.bias + col);
        float2 r = *(const float2*)(g.resid + (size_t)row * Ncols + col);
        x += b.x + r.x;
        y += b.y + r.y;
    } else if (g.epi == EPI_NORM) {
        float inv = 1.0f / g.bias[row];
        x *= inv;
        y *= inv;
    }
    if (g.Oh) {
        *(__half2*)(g.Oh + (size_t)row * Ncols + col) = __floats2half2_rn(x, y);
    } else {
        float2 v; v.x = x; v.y = y;
        *(float2*)(g.C + (size_t)row * Ncols + col) = v;
    }
}

#define ROWB 144                      // 64 fp16 (128B) + 16B pad
#define STAGE_B (256 * ROWB)          // A(128 rows) + B(128 rows) = 36 KB
#define NSTG 3
#define SMEM_GEMM (NSTG * STAGE_B)    // 108 KB; 2 CTAs/SM = 216 KB

__global__ __launch_bounds__(256, 2) void hmma_gemm(GArgs args, int Kd, int Ncols)
{
    constexpr uint32_t offA = 0;
    constexpr uint32_t offB = 128 * ROWB;

    extern __shared__ __align__(16) char smem[];
    const GArg g = args.a[blockIdx.z];
    const int tid = threadIdx.x;
    const int wid = tid >> 5, lane = tid & 31;
    const int bm = (g.swap ? blockIdx.x : blockIdx.y) << 7;
    const int bn = (g.swap ? blockIdx.y : blockIdx.x) << 7;
    const uint32_t sb = smem_u32(smem);

    const int r0 = tid >> 2, u0 = tid & 3;

    const int wr = wid >> 2, wc = wid & 3;   // warps 2 x 4
    const int m0 = wr << 6, n0 = wc << 5;    // warp tile 64 x 32

    float acc[4][4][4];
#pragma unroll
    for (int i = 0; i < 4; i++)
#pragma unroll
        for (int j = 0; j < 4; j++)
#pragma unroll
            for (int q = 0; q < 4; q++) acc[i][j][q] = 0.f;

    const int nIter = Kd >> 6;

    const uint32_t a_row = (uint32_t)(m0 + (lane & 15));
    const uint32_t a_colb = (uint32_t)((lane >> 4) << 4);
    const uint32_t b_row = (uint32_t)(n0 + (lane & 7) + ((lane >> 4) << 3));
    const uint32_t b_colb = (uint32_t)(((lane >> 3) & 1) << 4);

    auto load_stage = [&](int it, int buf) {
        const int k0 = it << 6;
        const uint32_t base = sb + (uint32_t)buf * (uint32_t)STAGE_B;
#pragma unroll
        for (int t = 0; t < 2; t++) {
            const int rr = r0 + (t << 6);
#pragma unroll
            for (int c = 0; c < 2; c++) {
                const int u = u0 + (c << 2);
                const uint32_t sa = base + (uint32_t)(rr * ROWB + (u << 4));
                cpasync16(sa + offA, g.Ah + (size_t)(bm + rr) * Kd + k0 + (u << 3));
                cpasync16(sa + offB, g.Bh + (size_t)(bn + rr) * Kd + k0 + (u << 3));
            }
        }
    };

    // prologue: stages 0, 1 in flight (2 committed groups)
    load_stage(0, 0); cp_commit();
    if (nIter > 1) load_stage(1, 1);
    cp_commit();

    int buf = 0;
    for (int it = 0; it < nIter; it++) {
        cp_wait<1>();           // stage `it` resident (1 younger group may fly)
        __syncthreads();        // all warps done reading stage it-1's slot
        if (it + 2 < nIter) load_stage(it + 2, (buf + 2) % NSTG);
        cp_commit();            // always commit: exactly 1 group per iteration

        const uint32_t base = sb + (uint32_t)buf * (uint32_t)STAGE_B;
#pragma unroll
        for (int kk = 0; kk < 4; kk++) {
            const uint32_t kb = (uint32_t)(kk << 5);
            uint32_t ah[4][4], bb[4][2];
#pragma unroll
            for (int i = 0; i < 4; i++) {
                uint32_t ad = base + offA + (a_row + (uint32_t)(i << 4)) * ROWB + kb + a_colb;
                ldmx4(ah[i], ad);
            }
#pragma unroll
            for (int p = 0; p < 2; p++) {
                uint32_t bd = base + offB + (b_row + (uint32_t)(p << 4)) * ROWB + kb + b_colb;
                uint32_t th[4];
                ldmx4(th, bd);
                bb[2 * p][0] = th[0]; bb[2 * p][1] = th[1];
                bb[2 * p + 1][0] = th[2]; bb[2 * p + 1][1] = th[3];
            }
#pragma unroll
            for (int i = 0; i < 4; i++)
#pragma unroll
                for (int j = 0; j < 4; j++)
                    mma16816(acc[i][j], ah[i], bb[j]);
        }
        buf = (buf + 1) % NSTG;
    }

    // ---------------- epilogue ----------------
    const int erow = bm + m0 + (lane >> 2);
    const int ecol = bn + n0 + ((lane & 3) << 1);

    if (g.epi == EPI_GAUSS || g.epi == EPI_BIAS) {
        // softmax numerator: e = exp(score*scale + bias - 8*ln2), fp16 out +
        // fp32 per-row sums atomically accumulated into g.C
        const bool gauss = (g.epi == EPI_GAUSS);
        const float SH = -5.5451774444795624f;   // -8*ln2 (overflow headroom)
#pragma unroll
        for (int i = 0; i < 4; i++) {
            const int ra = erow + (i << 4);
            const int rb = ra + 8;
            float rsa = 0.f, rsb = 0.f;
#pragma unroll
            for (int j = 0; j < 4; j++) {
                const int c = ecol + (j << 3);
                float2 b0 = *(const float2*)(g.bias + (size_t)ra * Ncols + c);
                float2 b1 = *(const float2*)(g.bias + (size_t)rb * Ncols + c);
                if (gauss) {
                    b0.x = __expf(-b0.x * b0.x * 0.005f);
                    b0.y = __expf(-b0.y * b0.y * 0.005f);
                    b1.x = __expf(-b1.x * b1.x * 0.005f);
                    b1.y = __expf(-b1.y * b1.y * 0.005f);
                }
                float e00 = __expf(acc[i][j][0] * g.scale + b0.x + SH);
                float e01 = __expf(acc[i][j][1] * g.scale + b0.y + SH);
                float e10 = __expf(acc[i][j][2] * g.scale + b1.x + SH);
                float e11 = __expf(acc[i][j][3] * g.scale + b1.y + SH);
                rsa += e00 + e01;
                rsb += e10 + e11;
                *(__half2*)(g.Oh + (size_t)ra * Ncols + c) = __floats2half2_rn(e00, e01);
                *(__half2*)(g.Oh + (size_t)rb * Ncols + c) = __floats2half2_rn(e10, e11);
            }
            rsa += __shfl_xor_sync(0xffffffffu, rsa, 1);
            rsa += __shfl_xor_sync(0xffffffffu, rsa, 2);
            rsb += __shfl_xor_sync(0xffffffffu, rsb, 1);
            rsb += __shfl_xor_sync(0xffffffffu, rsb, 2);
            if ((lane & 3) == 0) {
                atomicAdd(g.C + ra, rsa);
                atomicAdd(g.C + rb, rsb);
            }
        }
    } else {
#pragma unroll
        for (int i = 0; i < 4; i++)
#pragma unroll
            for (int j = 0; j < 4; j++) {
                const int r = erow + (i << 4);
                const int c = ecol + (j << 3);
                emit2(g, r,     c, acc[i][j][0], acc[i][j][1], Ncols);
                emit2(g, r + 8, c, acc[i][j][2], acc[i][j][3], Ncols);
            }
    }
}

// ---------------- batched layernorm over 512 -------------------------------
struct LnArgs {
    const float* X[2]; const float* R[2]; const float* gg[2]; const float* bb[2];
    float* out[2]; __half* oh[2];
};

__global__ __launch_bounds__(128) void layernorm_kernel(LnArgs a)
{
    const int z = blockIdx.y;
    const int row = blockIdx.x, tid = threadIdx.x;
    const int lane = tid & 31, warp = tid >> 5;
    __shared__ float red[4];

    float4 x = ((const float4*)(a.X[z] + (size_t)row * D_DIM))[tid];
    if (a.R[z]) {
        float4 r = ((const float4*)(a.R[z] + (size_t)row * D_DIM))[tid];
        x.x += r.x; x.y += r.y; x.z += r.z; x.w += r.w;
    }
    float s = x.x + x.y + x.z + x.w;
#pragma unroll
    for (int o = 16; o; o >>= 1) s += __shfl_xor_sync(0xffffffffu, s, o);
    if (lane == 0) red[warp] = s;
    __syncthreads();
    s = red[0] + red[1] + red[2] + red[3];
    const float mean = s * (1.0f / (float)D_DIM);

    const float dx = x.x - mean, dy = x.y - mean, dz = x.z - mean, dw = x.w - mean;
    float q = dx * dx + dy * dy + dz * dz + dw * dw;
    __syncthreads();
#pragma unroll
    for (int o = 16; o; o >>= 1) q += __shfl_xor_sync(0xffffffffu, q, o);
    if (lane == 0) red[warp] = q;
    __syncthreads();
    q = red[0] + red[1] + red[2] + red[3];

    const float rstd = rsqrtf(q * (1.0f / (float)D_DIM) + 1e-5f);
    float4 gg = ((const float4*)a.gg[z])[tid];
    float4 bb = ((const float4*)a.bb[z])[tid];
    float4 o4;
    o4.x = dx * rstd * gg.x + bb.x;
    o4.y = dy * rstd * gg.y + bb.y;
    o4.z = dz * rstd * gg.z + bb.z;
    o4.w = dw * rstd * gg.w + bb.w;
    ((float4*)(a.out[z] + (size_t)row * D_DIM))[tid] = o4;
    if (a.oh[z]) {
        size_t o = (size_t)row * D_DIM + tid * 4;
        *(__half2*)(a.oh[z] + o)     = __floats2half2_rn(o4.x, o4.y);
        *(__half2*)(a.oh[z] + o + 2) = __floats2half2_rn(o4.z, o4.w);
    }
}

// ---------------- host side -------------------------------------------------
template<typename T> static T* sym(const void* symbol) {
    void* p = nullptr;
    cudaGetSymbolAddress(&p, symbol);
    return (T*)p;
}

extern "C" void kernel_launch(void* const* d_in, const int* in_sizes, int n_in,
                              void* d_out, int out_size)
{
    (void)in_sizes; (void)n_in; (void)out_size;
    typedef __half hf;

    float* X1[2] = { sym<float>(g_X1), sym<float>(g_X1) + ND };
    float* X2[2] = { sym<float>(g_X2), sym<float>(g_X2) + ND };
    float* RS[2] = { sym<float>(g_rsum), sym<float>(g_rsum) + N_TOK };
    hf* Lh = sym<hf>(g_Lh);
    hf* Rh = sym<hf>(g_Rh);
    hf* Qh[2]  = { sym<hf>(g_Qh),  sym<hf>(g_Qh)  + ND };
    hf* Kh[2]  = { sym<hf>(g_Kh),  sym<hf>(g_Kh)  + ND };
    hf* Vth[2] = { sym<hf>(g_Vth), sym<hf>(g_Vth) + ND };
    hf* Sh[2]  = { sym<hf>(g_Sh),  sym<hf>(g_Sh)  + NN };
    hf* X2h[2] = { sym<hf>(g_X2h), sym<hf>(g_X2h) + ND };
    hf* Hh[2]  = { sym<hf>(g_Hh),  sym<hf>(g_Hh)  + ND };
    hf* Wth = sym<hf>(g_Wth);

    static bool attrs_done = false;
    if (!attrs_done) {
        cudaFuncSetAttribute((const void*)hmma_gemm, cudaFuncAttributeMaxDynamicSharedMemorySize, SMEM_GEMM);
        attrs_done = true;
    }

    const float* R  = (const float*)d_in[0];
    const float* L  = (const float*)d_in[1];
    const float* Dg = (const float*)d_in[2];
    const float* De = (const float*)d_in[3];
    const float* W5[2][5] = {
        { (const float*)d_in[4],  (const float*)d_in[5],  (const float*)d_in[6],
          (const float*)d_in[9],  (const float*)d_in[11] },
        { (const float*)d_in[15], (const float*)d_in[16], (const float*)d_in[17],
          (const float*)d_in[20], (const float*)d_in[22] },
    };
    const float* ln1g[2] = { (const float*)d_in[7],  (const float*)d_in[18] };
    const float* ln1b[2] = { (const float*)d_in[8],  (const float*)d_in[19] };
    const float* fb1[2]  = { (const float*)d_in[10], (const float*)d_in[21] };
    const float* fb2[2]  = { (const float*)d_in[12], (const float*)d_in[23] };
    const float* ln2g[2] = { (const float*)d_in[13], (const float*)d_in[24] };
    const float* ln2b[2] = { (const float*)d_in[14], (const float*)d_in[25] };
    const float* biasM[2] = { De, Dg };
    const float* resid[2] = { R, L };
    float* out = (float*)d_out;
    float* outp[2] = { out, out + (size_t)ND };

    const float scale = 0.04419417382415922f;  // 1/sqrt(512)

    // 0. zero the softmax row-sum accumulators
    cudaMemsetAsync(RS[0], 0, 2 * N_TOK * sizeof(float));

    // 1. convert the two token matrices to fp16
    {
        CvArgs ca{};
        ca.in[0] = L; ca.o[0] = Lh;
        ca.in[1] = R; ca.o[1] = Rh;
        cvt_kernel<<<dim3(ND / 4 / 256, 2), 256>>>(ca, ND / 4);
    }

    // 2. transpose+convert all 10 weight matrices
    {
        TcArgs t{};
        for (int b = 0; b < 2; b++)
            for (int w = 0; w < 5; w++) {
                t.in[b * 5 + w] = W5[b][w];
                t.oh[b * 5 + w] = Wth + (size_t)(b * 5 + w) * WSZ;
            }
        tconv_kernel<<<dim3(16, 16, 10), dim3(32, 8)>>>(t, D_DIM, D_DIM);
    }

    auto wt = [&](int b, int w) { return Wth + (size_t)(b * 5 + w) * WSZ; };

    // 3. Q, K projections for both branches, z = 0..3
    {
        GArgs ga{};
        for (int b = 0; b < 2; b++) {
            const hf* qh = b ? Rh : Lh;
            const hf* kh = b ? Lh : Rh;
            ga.a[b * 2 + 0] = { qh, wt(b, 0), nullptr, Qh[b], nullptr, nullptr, 0.f, EPI_NONE, 0 };
            ga.a[b * 2 + 1] = { kh, wt(b, 1), nullptr, Kh[b], nullptr, nullptr, 0.f, EPI_NONE, 0 };
        }
        hmma_gemm<<<dim3(D_DIM / 128, N_TOK / 128, 4), 256, SMEM_GEMM>>>(ga, D_DIM, D_DIM);
    }

    // 3b. V^T directly: A = Wv^T (M=512), B = KV source (N=4096)
    {
        GArgs ga{};
        for (int b = 0; b < 2; b++) {
            const hf* kh = b ? Lh : Rh;
            ga.a[b] = { wt(b, 2), kh, nullptr, Vth[b], nullptr, nullptr, 0.f, EPI_NONE, 1 };
        }
        hmma_gemm<<<dim3(D_DIM / 128, N_TOK / 128, 2), 256, SMEM_GEMM>>>(ga, D_DIM, N_TOK);
    }

    // 4. scores with fused exp + rowsum accumulation -> Sh fp16
    {
        GArgs ga{};
        ga.a[0] = { Qh[0], Kh[0], RS[0], Sh[0], biasM[0], nullptr, scale, EPI_GAUSS, 0 };
        ga.a[1] = { Qh[1], Kh[1], RS[1], Sh[1], biasM[1], nullptr, scale, EPI_BIAS, 0 };
        hmma_gemm<<<dim3(N_TOK / 128, N_TOK / 128, 2), 256, SMEM_GEMM>>>(ga, D_DIM, N_TOK);
    }

    // 5. att @ V with fused normalization -> X1 fp32
    {
        GArgs ga{};
        for (int b = 0; b < 2; b++)
            ga.a[b] = { Sh[b], Vth[b], X1[b], nullptr, RS[b], nullptr, 0.f, EPI_NORM, 0 };
        hmma_gemm<<<dim3(D_DIM / 128, N_TOK / 128, 2), 256, SMEM_GEMM>>>(ga, N_TOK, D_DIM);
    }

    // 6. LN1 (resid fused) -> X2 fp32 + fp16
    {
        LnArgs la{};
        for (int b = 0; b < 2; b++) {
            la.X[b] = X1[b]; la.R[b] = resid[b]; la.gg[b] = ln1g[b]; la.bb[b] = ln1b[b];
            la.out[b] = X2[b]; la.oh[b] = X2h[b];
        }
        layernorm_kernel<<<dim3(N_TOK, 2), 128>>>(la);
    }

    // 7. FFN1 (bias + relu) -> H fp16
    {
        GArgs ga{};
        for (int b = 0; b < 2; b++)
            ga.a[b] = { X2h[b], wt(b, 3), nullptr, Hh[b], fb1[b], nullptr, 0.f, EPI_RELU, 0 };
        hmma_gemm<<<dim3(D_DIM / 128, N_TOK / 128, 2), 256, SMEM_GEMM>>>(ga, D_DIM, D_DIM);
    }

    // 8. FFN2 (bias + residual X2) -> X1 fp32
    {
        GArgs ga{};
        for (int b = 0; b < 2; b++)
            ga.a[b] = { Hh[b], wt(b, 4), X1[b], nullptr, fb2[b], X2[b], 0.f, EPI_RESID, 0 };
        hmma_gemm<<<dim3(D_DIM / 128, N_TOK / 128, 2), 256, SMEM_GEMM>>>(ga, D_DIM, D_DIM);
    }

    // 9. LN2 -> final outputs
    {
        LnArgs la{};
        for (int b = 0; b < 2; b++) {
            la.X[b] = X1[b]; la.R[b] = nullptr; la.gg[b] = ln2g[b]; la.bb[b] = ln2b[b];
            la.out[b] = outp[b]; la.oh[b] = nullptr;
        }
        layernorm_kernel<<<dim3(N_TOK, 2), 128>>>(la);
    }
}

// round 17
// speedup vs baseline: 1.0267x; 1.0267x over previous
#include <cuda_runtime.h>
#include <cuda_fp16.h>
#include <cstdint>
#include <math.h>

#define N_TOK 4096
#define D_DIM 512
#define ND (N_TOK * D_DIM)
#define NN ((size_t)N_TOK * N_TOK)
#define WSZ (D_DIM * D_DIM)

// ---------------- scratch (device globals; no cudaMalloc allowed) ----------
static __device__ float g_X1[2][ND];
static __device__ float g_X2[2][ND];
static __device__ float g_rsum[2][N_TOK];

static __device__ __align__(16) __half g_Lh[ND], g_Rh[ND];
static __device__ __align__(16) __half g_Qh[2][ND], g_Kh[2][ND];
static __device__ __align__(16) __half g_Vth[2][ND];
static __device__ __align__(16) __half g_Sh[2][NN];
static __device__ __align__(16) __half g_X2h[2][ND];
static __device__ __align__(16) __half g_Hh[2][ND];
static __device__ __align__(16) __half g_Wth[10][WSZ];

// ---------------- helpers ---------------------------------------------------
__device__ __forceinline__ uint32_t smem_u32(const void* p) {
    uint32_t a;
    asm("{ .reg .u64 t; cvta.to.shared.u64 t, %1; cvt.u32.u64 %0, t; }" : "=r"(a) : "l"(p));
    return a;
}
__device__ __forceinline__ void cpasync16(uint32_t s, const void* g) {
    asm volatile("cp.async.cg.shared.global [%0], [%1], 16;" :: "r"(s), "l"(g) : "memory");
}
__device__ __forceinline__ void cp_commit() {
    asm volatile("cp.async.commit_group;" ::: "memory");
}
__device__ __forceinline__ void cp_wait_all() {
    asm volatile("cp.async.wait_group 0;" ::: "memory");
}
__device__ __forceinline__ void ldmx4(uint32_t* r, uint32_t a) {
    asm volatile("ldmatrix.sync.aligned.m8n8.x4.shared.b16 {%0,%1,%2,%3}, [%4];"
                 : "=r"(r[0]), "=r"(r[1]), "=r"(r[2]), "=r"(r[3]) : "r"(a));
}
__device__ __forceinline__ void mma16816(float* c, const uint32_t* a, const uint32_t* b) {
    asm volatile(
        "mma.sync.aligned.m16n8k16.row.col.f32.f16.f16.f32 "
        "{%0,%1,%2,%3},{%4,%5,%6,%7},{%8,%9},{%0,%1,%2,%3};"
        : "+f"(c[0]), "+f"(c[1]), "+f"(c[2]), "+f"(c[3])
        : "r"(a[0]), "r"(a[1]), "r"(a[2]), "r"(a[3]), "r"(b[0]), "r"(b[1]));
}

// ---------------- elementwise fp32 -> fp16 convert (batched) ---------------
struct CvArgs { const float* in[2]; __half* o[2]; };

__global__ __launch_bounds__(256) void cvt_kernel(CvArgs a, int n4)
{
    const float* __restrict__ in = a.in[blockIdx.y];
    __half* __restrict__ o = a.o[blockIdx.y];
    int i = blockIdx.x * 256 + threadIdx.x;
    if (i >= n4) return;
    float4 v = ((const float4*)in)[i];
    ((__half2*)o)[2 * i]     = __floats2half2_rn(v.x, v.y);
    ((__half2*)o)[2 * i + 1] = __floats2half2_rn(v.z, v.w);
}

// ---------------- batched transpose + convert (weights only) ---------------
struct TcArgs { const float* in[10]; __half* oh[10]; };

__global__ void tconv_kernel(TcArgs a, int rows, int cols)
{
    const float* __restrict__ in = a.in[blockIdx.z];
    __half* __restrict__ oh = a.oh[blockIdx.z];
    __shared__ float t[32][33];
    const int bx = blockIdx.x << 5, by = blockIdx.y << 5;
    const int tx = threadIdx.x, ty = threadIdx.y;  // 32 x 8
#pragma unroll
    for (int j = 0; j < 32; j += 8)
        t[ty + j][tx] = in[(size_t)(by + ty + j) * cols + bx + tx];
    __syncthreads();
#pragma unroll
    for (int j = 0; j < 32; j += 8) {
        float v = t[tx][ty + j];
        oh[(size_t)(bx + ty + j) * rows + by + tx] = __float2half_rn(v);
    }
}

// ---------------- HMMA fp16 GEMM (batched via grid.z) ----------------------
// C[M,N] = A[M,K] @ B[N,K]^T, fp16 operands, fp32 accum.
// CTA 128x128, BK=64, 8 warps (2x4), warp 64x32, 2-stage cp.async, 2 CTAs/SM.
// Kd/Ncols live in GArg so differently-shaped GEMMs can share one launch.
// swap=1: blockIdx.x indexes M-tiles, blockIdx.y indexes N-tiles.
enum { EPI_NONE = 0, EPI_GAUSS = 1, EPI_BIAS = 2, EPI_RELU = 3, EPI_RESID = 4, EPI_NORM = 5 };

struct GArg {
    const __half *Ah, *Bh;
    float* C;              // fp32 out (or rowsum accumulator for score epis)
    __half* Oh;            // fp16 out
    const float* bias;     // bias matrix / bias vec / rowsum (EPI_NORM)
    const float* resid;
    float scale;
    int epi;
    int swap;
    int Kd;
    int Ncols;
};
struct GArgs { GArg a[6]; };

__device__ __forceinline__ void emit2(const GArg& g, int row, int col, float x, float y, int Ncols)
{
    if (g.epi == EPI_RELU) {
        float2 b = *(const float2*)(g.bias + col);
        x = fmaxf(x + b.x, 0.f);
        y = fmaxf(y + b.y, 0.f);
    } else if (g.epi == EPI_RESID) {
        float2 b = *(const float2*)(g.bias + col);
        float2 r = *(const float2*)(g.resid + (size_t)row * Ncols + col);
        x += b.x + r.x;
        y += b.y + r.y;
    } else if (g.epi == EPI_NORM) {
        float inv = 1.0f / g.bias[row];
        x *= inv;
        y *= inv;
    }
    if (g.Oh) {
        *(__half2*)(g.Oh + (size_t)row * Ncols + col) = __floats2half2_rn(x, y);
    } else {
        float2 v; v.x = x; v.y = y;
        *(float2*)(g.C + (size_t)row * Ncols + col) = v;
    }
}

#define ROWB 144                      // 64 fp16 (128B) + 16B pad
#define STAGE_B (256 * ROWB)          // A(128 rows) + B(128 rows) = 36 KB
#define SMEM_GEMM (2 * STAGE_B)       // 2 stages = 72 KB; 2 CTAs/SM

__global__ __launch_bounds__(256, 2) void hmma_gemm(GArgs args)
{
    constexpr uint32_t offA = 0;
    constexpr uint32_t offB = 128 * ROWB;

    extern __shared__ __align__(16) char smem[];
    const GArg g = args.a[blockIdx.z];
    const int Kd = g.Kd, Ncols = g.Ncols;
    const int tid = threadIdx.x;
    const int wid = tid >> 5, lane = tid & 31;
    const int bm = (g.swap ? blockIdx.x : blockIdx.y) << 7;
    const int bn = (g.swap ? blockIdx.y : blockIdx.x) << 7;
    const uint32_t sb = smem_u32(smem);

    const int r0 = tid >> 2, u0 = tid & 3;

    const int wr = wid >> 2, wc = wid & 3;   // warps 2 x 4
    const int m0 = wr << 6, n0 = wc << 5;    // warp tile 64 x 32

    float acc[4][4][4];
#pragma unroll
    for (int i = 0; i < 4; i++)
#pragma unroll
        for (int j = 0; j < 4; j++)
#pragma unroll
            for (int q = 0; q < 4; q++) acc[i][j][q] = 0.f;

    const int nIter = Kd >> 6;

    const uint32_t a_row = (uint32_t)(m0 + (lane & 15));
    const uint32_t a_colb = (uint32_t)((lane >> 4) << 4);
    const uint32_t b_row = (uint32_t)(n0 + (lane & 7) + ((lane >> 4) << 3));
    const uint32_t b_colb = (uint32_t)(((lane >> 3) & 1) << 4);

    auto load_stage = [&](int it, int buf) {
        const int k0 = it << 6;
        const uint32_t base = sb + (uint32_t)buf * (uint32_t)STAGE_B;
#pragma unroll
        for (int t = 0; t < 2; t++) {
            const int rr = r0 + (t << 6);
#pragma unroll
            for (int c = 0; c < 2; c++) {
                const int u = u0 + (c << 2);
                const uint32_t sa = base + (uint32_t)(rr * ROWB + (u << 4));
                cpasync16(sa + offA, g.Ah + (size_t)(bm + rr) * Kd + k0 + (u << 3));
                cpasync16(sa + offB, g.Bh + (size_t)(bn + rr) * Kd + k0 + (u << 3));
            }
        }
        cp_commit();
    };

    load_stage(0, 0);

    int buf = 0;
    for (int it = 0; it < nIter; it++) {
        cp_wait_all();
        __syncthreads();
        // prefetch next stage into buffer freed by iteration it-1
        if (it + 1 < nIter) load_stage(it + 1, buf ^ 1);

        const uint32_t base = sb + (uint32_t)buf * (uint32_t)STAGE_B;
#pragma unroll
        for (int kk = 0; kk < 4; kk++) {
            const uint32_t kb = (uint32_t)(kk << 5);
            uint32_t ah[4][4], bb[4][2];
#pragma unroll
            for (int i = 0; i < 4; i++) {
                uint32_t ad = base + offA + (a_row + (uint32_t)(i << 4)) * ROWB + kb + a_colb;
                ldmx4(ah[i], ad);
            }
#pragma unroll
            for (int p = 0; p < 2; p++) {
                uint32_t bd = base + offB + (b_row + (uint32_t)(p << 4)) * ROWB + kb + b_colb;
                uint32_t th[4];
                ldmx4(th, bd);
                bb[2 * p][0] = th[0]; bb[2 * p][1] = th[1];
                bb[2 * p + 1][0] = th[2]; bb[2 * p + 1][1] = th[3];
            }
#pragma unroll
            for (int i = 0; i < 4; i++)
#pragma unroll
                for (int j = 0; j < 4; j++)
                    mma16816(acc[i][j], ah[i], bb[j]);
        }
        buf ^= 1;
    }

    // ---------------- epilogue ----------------
    const int erow = bm + m0 + (lane >> 2);
    const int ecol = bn + n0 + ((lane & 3) << 1);

    if (g.epi == EPI_GAUSS || g.epi == EPI_BIAS) {
        // softmax numerator: e = exp(score*scale + bias - 8*ln2), fp16 out +
        // fp32 per-row sums atomically accumulated into g.C
        const bool gauss = (g.epi == EPI_GAUSS);
        const float SH = -5.5451774444795624f;   // -8*ln2 (overflow headroom)
#pragma unroll
        for (int i = 0; i < 4; i++) {
            const int ra = erow + (i << 4);
            const int rb = ra + 8;
            float rsa = 0.f, rsb = 0.f;
#pragma unroll
            for (int j = 0; j < 4; j++) {
                const int c = ecol + (j << 3);
                float2 b0 = *(const float2*)(g.bias + (size_t)ra * Ncols + c);
                float2 b1 = *(const float2*)(g.bias + (size_t)rb * Ncols + c);
                if (gauss) {
                    b0.x = __expf(-b0.x * b0.x * 0.005f);
                    b0.y = __expf(-b0.y * b0.y * 0.005f);
                    b1.x = __expf(-b1.x * b1.x * 0.005f);
                    b1.y = __expf(-b1.y * b1.y * 0.005f);
                }
                float e00 = __expf(acc[i][j][0] * g.scale + b0.x + SH);
                float e01 = __expf(acc[i][j][1] * g.scale + b0.y + SH);
                float e10 = __expf(acc[i][j][2] * g.scale + b1.x + SH);
                float e11 = __expf(acc[i][j][3] * g.scale + b1.y + SH);
                rsa += e00 + e01;
                rsb += e10 + e11;
                *(__half2*)(g.Oh + (size_t)ra * Ncols + c) = __floats2half2_rn(e00, e01);
                *(__half2*)(g.Oh + (size_t)rb * Ncols + c) = __floats2half2_rn(e10, e11);
            }
            rsa += __shfl_xor_sync(0xffffffffu, rsa, 1);
            rsa += __shfl_xor_sync(0xffffffffu, rsa, 2);
            rsb += __shfl_xor_sync(0xffffffffu, rsb, 1);
            rsb += __shfl_xor_sync(0xffffffffu, rsb, 2);
            if ((lane & 3) == 0) {
                atomicAdd(g.C + ra, rsa);
                atomicAdd(g.C + rb, rsb);
            }
        }
    } else {
#pragma unroll
        for (int i = 0; i < 4; i++)
#pragma unroll
            for (int j = 0; j < 4; j++) {
                const int r = erow + (i << 4);
                const int c = ecol + (j << 3);
                emit2(g, r,     c, acc[i][j][0], acc[i][j][1], Ncols);
                emit2(g, r + 8, c, acc[i][j][2], acc[i][j][3], Ncols);
            }
    }
}

// ---------------- batched layernorm over 512 -------------------------------
struct LnArgs {
    const float* X[2]; const float* R[2]; const float* gg[2]; const float* bb[2];
    float* out[2]; __half* oh[2];
};

__global__ __launch_bounds__(128) void layernorm_kernel(LnArgs a)
{
    const int z = blockIdx.y;
    const int row = blockIdx.x, tid = threadIdx.x;
    const int lane = tid & 31, warp = tid >> 5;
    __shared__ float red[4];

    float4 x = ((const float4*)(a.X[z] + (size_t)row * D_DIM))[tid];
    if (a.R[z]) {
        float4 r = ((const float4*)(a.R[z] + (size_t)row * D_DIM))[tid];
        x.x += r.x; x.y += r.y; x.z += r.z; x.w += r.w;
    }
    float s = x.x + x.y + x.z + x.w;
#pragma unroll
    for (int o = 16; o; o >>= 1) s += __shfl_xor_sync(0xffffffffu, s, o);
    if (lane == 0) red[warp] = s;
    __syncthreads();
    s = red[0] + red[1] + red[2] + red[3];
    const float mean = s * (1.0f / (float)D_DIM);

    const float dx = x.x - mean, dy = x.y - mean, dz = x.z - mean, dw = x.w - mean;
    float q = dx * dx + dy * dy + dz * dz + dw * dw;
    __syncthreads();
#pragma unroll
    for (int o = 16; o; o >>= 1) q += __shfl_xor_sync(0xffffffffu, q, o);
    if (lane == 0) red[warp] = q;
    __syncthreads();
    q = red[0] + red[1] + red[2] + red[3];

    const float rstd = rsqrtf(q * (1.0f / (float)D_DIM) + 1e-5f);
    float4 gg = ((const float4*)a.gg[z])[tid];
    float4 bb = ((const float4*)a.bb[z])[tid];
    float4 o4;
    o4.x = dx * rstd * gg.x + bb.x;
    o4.y = dy * rstd * gg.y + bb.y;
    o4.z = dz * rstd * gg.z + bb.z;
    o4.w = dw * rstd * gg.w + bb.w;
    ((float4*)(a.out[z] + (size_t)row * D_DIM))[tid] = o4;
    if (a.oh[z]) {
        size_t o = (size_t)row * D_DIM + tid * 4;
        *(__half2*)(a.oh[z] + o)     = __floats2half2_rn(o4.x, o4.y);
        *(__half2*)(a.oh[z] + o + 2) = __floats2half2_rn(o4.z, o4.w);
    }
}

// ---------------- host side -------------------------------------------------
template<typename T> static T* sym(const void* symbol) {
    void* p = nullptr;
    cudaGetSymbolAddress(&p, symbol);
    return (T*)p;
}

extern "C" void kernel_launch(void* const* d_in, const int* in_sizes, int n_in,
                              void* d_out, int out_size)
{
    (void)in_sizes; (void)n_in; (void)out_size;
    typedef __half hf;

    float* X1[2] = { sym<float>(g_X1), sym<float>(g_X1) + ND };
    float* X2[2] = { sym<float>(g_X2), sym<float>(g_X2) + ND };
    float* RS[2] = { sym<float>(g_rsum), sym<float>(g_rsum) + N_TOK };
    hf* Lh = sym<hf>(g_Lh);
    hf* Rh = sym<hf>(g_Rh);
    hf* Qh[2]  = { sym<hf>(g_Qh),  sym<hf>(g_Qh)  + ND };
    hf* Kh[2]  = { sym<hf>(g_Kh),  sym<hf>(g_Kh)  + ND };
    hf* Vth[2] = { sym<hf>(g_Vth), sym<hf>(g_Vth) + ND };
    hf* Sh[2]  = { sym<hf>(g_Sh),  sym<hf>(g_Sh)  + NN };
    hf* X2h[2] = { sym<hf>(g_X2h), sym<hf>(g_X2h) + ND };
    hf* Hh[2]  = { sym<hf>(g_Hh),  sym<hf>(g_Hh)  + ND };
    hf* Wth = sym<hf>(g_Wth);

    static bool attrs_done = false;
    if (!attrs_done) {
        cudaFuncSetAttribute((const void*)hmma_gemm, cudaFuncAttributeMaxDynamicSharedMemorySize, SMEM_GEMM);
        attrs_done = true;
    }

    const float* R  = (const float*)d_in[0];
    const float* L  = (const float*)d_in[1];
    const float* Dg = (const float*)d_in[2];
    const float* De = (const float*)d_in[3];
    const float* W5[2][5] = {
        { (const float*)d_in[4],  (const float*)d_in[5],  (const float*)d_in[6],
          (const float*)d_in[9],  (const float*)d_in[11] },
        { (const float*)d_in[15], (const float*)d_in[16], (const float*)d_in[17],
          (const float*)d_in[20], (const float*)d_in[22] },
    };
    const float* ln1g[2] = { (const float*)d_in[7],  (const float*)d_in[18] };
    const float* ln1b[2] = { (const float*)d_in[8],  (const float*)d_in[19] };
    const float* fb1[2]  = { (const float*)d_in[10], (const float*)d_in[21] };
    const float* fb2[2]  = { (const float*)d_in[12], (const float*)d_in[23] };
    const float* ln2g[2] = { (const float*)d_in[13], (const float*)d_in[24] };
    const float* ln2b[2] = { (const float*)d_in[14], (const float*)d_in[25] };
    const float* biasM[2] = { De, Dg };
    const float* resid[2] = { R, L };
    float* out = (float*)d_out;
    float* outp[2] = { out, out + (size_t)ND };

    const float scale = 0.04419417382415922f;  // 1/sqrt(512)

    // 0. zero the softmax row-sum accumulators
    cudaMemsetAsync(RS[0], 0, 2 * N_TOK * sizeof(float));

    // 1. convert the two token matrices to fp16
    {
        CvArgs ca{};
        ca.in[0] = L; ca.o[0] = Lh;
        ca.in[1] = R; ca.o[1] = Rh;
        cvt_kernel<<<dim3(ND / 4 / 256, 2), 256>>>(ca, ND / 4);
    }

    // 2. transpose+convert all 10 weight matrices
    {
        TcArgs t{};
        for (int b = 0; b < 2; b++)
            for (int w = 0; w < 5; w++) {
                t.in[b * 5 + w] = W5[b][w];
                t.oh[b * 5 + w] = Wth + (size_t)(b * 5 + w) * WSZ;
            }
        tconv_kernel<<<dim3(16, 16, 10), dim3(32, 8)>>>(t, D_DIM, D_DIM);
    }

    auto wt = [&](int b, int w) { return Wth + (size_t)(b * 5 + w) * WSZ; };

    // 3. ALL projections in ONE launch (Kd/Ncols are per-slot now):
    //    z=0..3: Q/K  (x = N-tiles(4), y = M-tiles(32), Ncols=512)
    //    z=4..5: V^T  (swap: x = M-tiles(4), y = N-tiles(32), Ncols=4096)
    {
        GArgs ga{};
        for (int b = 0; b < 2; b++) {
            const hf* qh = b ? Rh : Lh;
            const hf* kh = b ? Lh : Rh;
            ga.a[b * 2 + 0] = { qh, wt(b, 0), nullptr, Qh[b], nullptr, nullptr, 0.f, EPI_NONE, 0, D_DIM, D_DIM };
            ga.a[b * 2 + 1] = { kh, wt(b, 1), nullptr, Kh[b], nullptr, nullptr, 0.f, EPI_NONE, 0, D_DIM, D_DIM };
            ga.a[4 + b]     = { wt(b, 2), kh, nullptr, Vth[b], nullptr, nullptr, 0.f, EPI_NONE, 1, D_DIM, N_TOK };
        }
        hmma_gemm<<<dim3(4, 32, 6), 256, SMEM_GEMM>>>(ga);
    }

    // 4. scores with fused exp + rowsum accumulation -> Sh fp16
    {
        GArgs ga{};
        ga.a[0] = { Qh[0], Kh[0], RS[0], Sh[0], biasM[0], nullptr, scale, EPI_GAUSS, 0, D_DIM, N_TOK };
        ga.a[1] = { Qh[1], Kh[1], RS[1], Sh[1], biasM[1], nullptr, scale, EPI_BIAS, 0, D_DIM, N_TOK };
        hmma_gemm<<<dim3(N_TOK / 128, N_TOK / 128, 2), 256, SMEM_GEMM>>>(ga);
    }

    // 5. att @ V with fused normalization -> X1 fp32
    {
        GArgs ga{};
        for (int b = 0; b < 2; b++)
            ga.a[b] = { Sh[b], Vth[b], X1[b], nullptr, RS[b], nullptr, 0.f, EPI_NORM, 0, N_TOK, D_DIM };
        hmma_gemm<<<dim3(D_DIM / 128, N_TOK / 128, 2), 256, SMEM_GEMM>>>(ga);
    }

    // 6. LN1 (resid fused) -> X2 fp32 + fp16
    {
        LnArgs la{};
        for (int b = 0; b < 2; b++) {
            la.X[b] = X1[b]; la.R[b] = resid[b]; la.gg[b] = ln1g[b]; la.bb[b] = ln1b[b];
            la.out[b] = X2[b]; la.oh[b] = X2h[b];
        }
        layernorm_kernel<<<dim3(N_TOK, 2), 128>>>(la);
    }

    // 7. FFN1 (bias + relu) -> H fp16
    {
        GArgs ga{};
        for (int b = 0; b < 2; b++)
            ga.a[b] = { X2h[b], wt(b, 3), nullptr, Hh[b], fb1[b], nullptr, 0.f, EPI_RELU, 0, D_DIM, D_DIM };
        hmma_gemm<<<dim3(D_DIM / 128, N_TOK / 128, 2), 256, SMEM_GEMM>>>(ga);
    }

    // 8. FFN2 (bias + residual X2) -> X1 fp32
    {
        GArgs ga{};
        for (int b = 0; b < 2; b++)
            ga.a[b] = { Hh[b], wt(b, 4), X1[b], nullptr, fb2[b], X2[b], 0.f, EPI_RESID, 0, D_DIM, D_DIM };
        hmma_gemm<<<dim3(D_DIM / 128, N_TOK / 128, 2), 256, SMEM_GEMM>>>(ga);
    }

    // 9. LN2 -> final outputs
    {
        LnArgs la{};
        for (int b = 0; b < 2; b++) {
            la.X[b] = X1[b]; la.R[b] = nullptr; la.gg[b] = ln2g[b]; la.bb[b] = ln2b[b];
            la.out[b] = outp[b]; la.oh[b] = nullptr;
        }
        layernorm_kernel<<<dim3(N_TOK, 2), 128>>>(la);
    }
}